// round 1
// baseline (speedup 1.0000x reference)
#include <cuda_runtime.h>

// Problem constants (fixed by the reference): N=1024 agents, H=64 hidden.
#define Nn 1024
#define Hh 64
#define EE (Nn * (Nn - 1))   // 1047552 edges

// Scratch for the factored first layer:
//   gA[i][k] = b1[k] + sum_c emb[i][c] * W1[c][k]        (top half of W1)
//   gB[j][k] =         sum_c emb[j][c] * W1[64+c][k]     (bottom half of W1)
__device__ float gA[Nn * Hh];
__device__ float gB[Nn * Hh];

// ---------------------------------------------------------------------------
// Kernel 1: C[1024 x 128] = emb[1024 x 64] @ [W1_top | W1_bot], split into gA/gB.
// 128 blocks x 256 threads; warp = one row, lanes cover the 128 output cols in
// float4 quads. Per-thread: 16 c-chunks x (1 emb float4 + 4 W1 float4 + 16 FFMA).
// ---------------------------------------------------------------------------
__global__ void prep_kernel(const float* __restrict__ emb,
                            const float* __restrict__ W1,
                            const float* __restrict__ b1) {
    const int t = threadIdx.x;
    const int row = blockIdx.x * 8 + (t >> 5);   // 8 rows per block
    const int lane = t & 31;
    const int m = lane * 4;                      // output col quad: 0..124
    const int half = m >> 6;                     // 0 -> gA, 1 -> gB
    const int k = m & 63;                        // col within half
    const float* w1base = W1 + half * Hh * Hh;

    float acc0 = 0.f, acc1 = 0.f, acc2 = 0.f, acc3 = 0.f;
#pragma unroll
    for (int c = 0; c < Hh; c += 4) {
        const float4 e4 = *reinterpret_cast<const float4*>(emb + row * Hh + c);
        const float4 w0 = *reinterpret_cast<const float4*>(w1base + (c + 0) * Hh + k);
        const float4 w1v = *reinterpret_cast<const float4*>(w1base + (c + 1) * Hh + k);
        const float4 w2v = *reinterpret_cast<const float4*>(w1base + (c + 2) * Hh + k);
        const float4 w3v = *reinterpret_cast<const float4*>(w1base + (c + 3) * Hh + k);
        acc0 = fmaf(e4.x, w0.x, acc0); acc0 = fmaf(e4.y, w1v.x, acc0);
        acc0 = fmaf(e4.z, w2v.x, acc0); acc0 = fmaf(e4.w, w3v.x, acc0);
        acc1 = fmaf(e4.x, w0.y, acc1); acc1 = fmaf(e4.y, w1v.y, acc1);
        acc1 = fmaf(e4.z, w2v.y, acc1); acc1 = fmaf(e4.w, w3v.y, acc1);
        acc2 = fmaf(e4.x, w0.z, acc2); acc2 = fmaf(e4.y, w1v.z, acc2);
        acc2 = fmaf(e4.z, w2v.z, acc2); acc2 = fmaf(e4.w, w3v.z, acc2);
        acc3 = fmaf(e4.x, w0.w, acc3); acc3 = fmaf(e4.y, w1v.w, acc3);
        acc3 = fmaf(e4.z, w2v.w, acc3); acc3 = fmaf(e4.w, w3v.w, acc3);
    }

    float4 o;
    if (half == 0) {
        const float4 bb = *reinterpret_cast<const float4*>(b1 + k);
        o.x = acc0 + bb.x; o.y = acc1 + bb.y; o.z = acc2 + bb.z; o.w = acc3 + bb.w;
        *reinterpret_cast<float4*>(&gA[row * Hh + k]) = o;
    } else {
        o.x = acc0; o.y = acc1; o.z = acc2; o.w = acc3;
        *reinterpret_cast<float4*>(&gB[row * Hh + k]) = o;
    }
}

// ---------------------------------------------------------------------------
// Kernel 2: per-pair MLP. Grid = 16x16 blocks, each block a 64(i) x 64(j) tile.
// 256 threads (tx=t%16 over j, ty=t/16 over i), 4x4 register micro-tile:
//   i = i0 + ty*4 + ii,  j = j0 + tx + 16*jj  (adjacent tx -> adjacent j ->
//   coalesced stores; skip at diagonal handled per element).
// SMEM tiles padded to stride 76 floats: 16B-aligned float4 rows AND
// conflict-free LDS.128 (lane byte-offsets mod 128 = {0,48,96,16,64,112,32,80}).
// ---------------------------------------------------------------------------
#define TPAD 76

__global__ void pair_kernel(const float* __restrict__ W2,
                            const float* __restrict__ b2ptr,
                            float* __restrict__ out) {
    __shared__ float sA[64 * TPAD];
    __shared__ float sB[64 * TPAD];
    __shared__ float sW2[64];

    const int t = threadIdx.x;
    const int tx = t & 15;
    const int ty = t >> 4;
    const int i0 = blockIdx.y * 64;
    const int j0 = blockIdx.x * 64;

    // Cooperative tile loads: 1024 float4 per tile, 4 per thread.
#pragma unroll
    for (int q = t; q < 64 * 16; q += 256) {
        const int row = q >> 4;
        const int c4 = (q & 15) * 4;
        *reinterpret_cast<float4*>(&sA[row * TPAD + c4]) =
            *reinterpret_cast<const float4*>(&gA[(i0 + row) * Hh + c4]);
        *reinterpret_cast<float4*>(&sB[row * TPAD + c4]) =
            *reinterpret_cast<const float4*>(&gB[(j0 + row) * Hh + c4]);
    }
    if (t < 64) sW2[t] = W2[t];
    __syncthreads();

    float acc[4][4] = {};

#pragma unroll 2
    for (int k = 0; k < 64; k += 4) {
        const float4 w4 = *reinterpret_cast<const float4*>(&sW2[k]);
        float4 a4[4], b4[4];
#pragma unroll
        for (int u = 0; u < 4; u++)
            a4[u] = *reinterpret_cast<const float4*>(&sA[(ty * 4 + u) * TPAD + k]);
#pragma unroll
        for (int u = 0; u < 4; u++)
            b4[u] = *reinterpret_cast<const float4*>(&sB[(tx + 16 * u) * TPAD + k]);

#pragma unroll
        for (int ii = 0; ii < 4; ii++) {
#pragma unroll
            for (int jj = 0; jj < 4; jj++) {
                float a = acc[ii][jj];
                a = fmaf(fmaxf(a4[ii].x + b4[jj].x, 0.f), w4.x, a);
                a = fmaf(fmaxf(a4[ii].y + b4[jj].y, 0.f), w4.y, a);
                a = fmaf(fmaxf(a4[ii].z + b4[jj].z, 0.f), w4.z, a);
                a = fmaf(fmaxf(a4[ii].w + b4[jj].w, 0.f), w4.w, a);
                acc[ii][jj] = a;
            }
        }
    }

    const float b2 = b2ptr[0];

#pragma unroll
    for (int ii = 0; ii < 4; ii++) {
        const int i = i0 + ty * 4 + ii;
#pragma unroll
        for (int jj = 0; jj < 4; jj++) {
            const int j = j0 + tx + 16 * jj;
            if (j == i) continue;
            // Reference ordering: e = i*(N-1) + (j if j<i else j-1)
            const int e = i * (Nn - 1) + j - (j > i ? 1 : 0);
            const float x = acc[ii][jj] + b2;
            const float w = 1.0f / (1.0f + __expf(-x));
            out[e] = (float)i;             // edge_index row 0
            out[EE + e] = (float)j;        // edge_index row 1
            out[2 * EE + e] = w;           // edge weight
        }
    }
}

extern "C" void kernel_launch(void* const* d_in, const int* in_sizes, int n_in,
                              void* d_out, int out_size) {
    const float* emb = (const float*)d_in[0];  // [1024, 64]
    const float* W1  = (const float*)d_in[1];  // [128, 64]
    const float* b1  = (const float*)d_in[2];  // [64]
    const float* W2  = (const float*)d_in[3];  // [64, 1]
    const float* b2  = (const float*)d_in[4];  // [1]
    float* out = (float*)d_out;

    prep_kernel<<<128, 256>>>(emb, W1, b1);
    pair_kernel<<<dim3(16, 16), 256>>>(W2, b2, out);
}

// round 2
// speedup vs baseline: 1.0311x; 1.0311x over previous
#include <cuda_runtime.h>

// Problem constants (fixed by the reference): N=1024 agents, H=64 hidden.
#define Nn 1024
#define Hh 64
#define EE (Nn * (Nn - 1))   // 1047552 edges

// Factored first layer:
//   gA[i][k] = b1[k] + sum_c emb[i][c] * W1[c][k]        (top half of W1)
//   gB[j][k] =         sum_c emb[j][c] * W1[64+c][k]     (bottom half of W1)
__device__ float gA[Nn * Hh];
__device__ float gB[Nn * Hh];

// ---- packed f32x2 helpers (sm_10x; ptxas never auto-fuses these) -----------
__device__ __forceinline__ float2 add2(float2 a, float2 b) {
    float2 d;
    asm("add.rn.f32x2 %0, %1, %2;"
        : "=l"(*reinterpret_cast<unsigned long long*>(&d))
        : "l"(*reinterpret_cast<const unsigned long long*>(&a)),
          "l"(*reinterpret_cast<const unsigned long long*>(&b)));
    return d;
}
__device__ __forceinline__ float2 fma2(float2 a, float2 b, float2 c) {
    float2 d;
    asm("fma.rn.f32x2 %0, %1, %2, %3;"
        : "=l"(*reinterpret_cast<unsigned long long*>(&d))
        : "l"(*reinterpret_cast<const unsigned long long*>(&a)),
          "l"(*reinterpret_cast<const unsigned long long*>(&b)),
          "l"(*reinterpret_cast<const unsigned long long*>(&c)));
    return d;
}

// ---------------------------------------------------------------------------
// Kernel 1: C[1024 x 128] = emb @ [W1_top | W1_bot] -> gA/gB, PLUS the two
// edge_index planes of the output (they depend on nothing computed — pure
// stores that overlap this latency-bound mini-GEMM).
// 128 blocks x 256 threads; warp = one emb row, lanes cover 128 output cols.
// ---------------------------------------------------------------------------
__global__ void prep_kernel(const float* __restrict__ emb,
                            const float* __restrict__ W1,
                            const float* __restrict__ b1,
                            float* __restrict__ out) {
    const int t = threadIdx.x;
    const int row = blockIdx.x * 8 + (t >> 5);
    const int lane = t & 31;
    const int m = lane * 4;
    const int half = m >> 6;
    const int k = m & 63;
    const float* w1base = W1 + half * Hh * Hh;

    float acc0 = 0.f, acc1 = 0.f, acc2 = 0.f, acc3 = 0.f;
#pragma unroll
    for (int c = 0; c < Hh; c += 4) {
        const float4 e4 = *reinterpret_cast<const float4*>(emb + row * Hh + c);
        const float4 w0 = *reinterpret_cast<const float4*>(w1base + (c + 0) * Hh + k);
        const float4 w1v = *reinterpret_cast<const float4*>(w1base + (c + 1) * Hh + k);
        const float4 w2v = *reinterpret_cast<const float4*>(w1base + (c + 2) * Hh + k);
        const float4 w3v = *reinterpret_cast<const float4*>(w1base + (c + 3) * Hh + k);
        acc0 = fmaf(e4.x, w0.x, acc0); acc0 = fmaf(e4.y, w1v.x, acc0);
        acc0 = fmaf(e4.z, w2v.x, acc0); acc0 = fmaf(e4.w, w3v.x, acc0);
        acc1 = fmaf(e4.x, w0.y, acc1); acc1 = fmaf(e4.y, w1v.y, acc1);
        acc1 = fmaf(e4.z, w2v.y, acc1); acc1 = fmaf(e4.w, w3v.y, acc1);
        acc2 = fmaf(e4.x, w0.z, acc2); acc2 = fmaf(e4.y, w1v.z, acc2);
        acc2 = fmaf(e4.z, w2v.z, acc2); acc2 = fmaf(e4.w, w3v.z, acc2);
        acc3 = fmaf(e4.x, w0.w, acc3); acc3 = fmaf(e4.y, w1v.w, acc3);
        acc3 = fmaf(e4.z, w2v.w, acc3); acc3 = fmaf(e4.w, w3v.w, acc3);
    }

    float4 o;
    if (half == 0) {
        const float4 bb = *reinterpret_cast<const float4*>(b1 + k);
        o.x = acc0 + bb.x; o.y = acc1 + bb.y; o.z = acc2 + bb.z; o.w = acc3 + bb.w;
        *reinterpret_cast<float4*>(&gA[row * Hh + k]) = o;
    } else {
        o.x = acc0; o.y = acc1; o.z = acc2; o.w = acc3;
        *reinterpret_cast<float4*>(&gB[row * Hh + k]) = o;
    }

    // --- edge_index planes: out[e] = i, out[E+e] = j ---
    // e = i*1023 + (j - (j>i));  inverse: i = e/1023, r = e%1023, j = r + (r>=i)
    const unsigned tid = blockIdx.x * 256 + t;       // 32768 threads
    const unsigned nquads = EE / 4;                  // 261888, 16B-aligned planes
#pragma unroll 4
    for (unsigned q = tid; q < nquads; q += 32768) {
        const unsigned e0 = q * 4;
        float4 vi, vj;
        float* pi = &vi.x;
        float* pj = &vj.x;
#pragma unroll
        for (int u = 0; u < 4; u++) {
            const unsigned e = e0 + u;
            const unsigned i = e / 1023u;            // umulhi path
            const unsigned r = e - i * 1023u;
            const unsigned j = r + (r >= i ? 1u : 0u);
            pi[u] = (float)i;
            pj[u] = (float)j;
        }
        *reinterpret_cast<float4*>(out + e0) = vi;
        *reinterpret_cast<float4*>(out + EE + e0) = vj;
    }
}

// ---------------------------------------------------------------------------
// Kernel 2: per-pair MLP. Grid 32x32 = 1024 CTAs (6.92 waves on 148 SMs,
// ~1% imbalance). Each CTA: 32(i) x 32(j) tile, 64 threads, 4x4 micro-tile
// with i = i0 + ty + 8*ii and j = j0 + tx + 8*jj (stride-8 rows -> SMEM
// accesses at stride 76 floats hit distinct mod-128 banks: conflict-free
// LDS.128 for both A and B).
// Inner math is packed f32x2: per 4 k per pair = 2 ADD2 + 4 FMNMX + 2 FMA2.
// ---------------------------------------------------------------------------
#define TS 32
#define TPAD 76

__global__ void __launch_bounds__(64) pair_kernel(const float* __restrict__ W2,
                                                  const float* __restrict__ b2ptr,
                                                  float* __restrict__ out) {
    __shared__ float sA[TS * TPAD];
    __shared__ float sB[TS * TPAD];
    __shared__ float sW2[64];

    const int t = threadIdx.x;
    const int tx = t & 7;
    const int ty = t >> 3;
    const int i0 = blockIdx.y * TS;
    const int j0 = blockIdx.x * TS;

    // Cooperative loads: 2 tiles x 512 float4 / 64 threads = 16 float4 each.
#pragma unroll
    for (int q = t; q < TS * 16; q += 64) {
        const int row = q >> 4;
        const int c4 = (q & 15) * 4;
        *reinterpret_cast<float4*>(&sA[row * TPAD + c4]) =
            *reinterpret_cast<const float4*>(&gA[(i0 + row) * Hh + c4]);
        *reinterpret_cast<float4*>(&sB[row * TPAD + c4]) =
            *reinterpret_cast<const float4*>(&gB[(j0 + row) * Hh + c4]);
    }
    sW2[t] = W2[t];   // 64 threads cover 64 weights
    __syncthreads();

    const float b2 = b2ptr[0];
    float2 acc[4][4];
#pragma unroll
    for (int ii = 0; ii < 4; ii++)
#pragma unroll
        for (int jj = 0; jj < 4; jj++)
            acc[ii][jj] = make_float2(b2, 0.f);   // fold b2 into the lo half

#pragma unroll 2
    for (int k = 0; k < Hh; k += 4) {
        const float4 wq = *reinterpret_cast<const float4*>(&sW2[k]);
        const float2 w01 = *reinterpret_cast<const float2*>(&wq.x);
        const float2 w23 = *reinterpret_cast<const float2*>(&wq.z);

        float4 av[4], bv[4];
#pragma unroll
        for (int u = 0; u < 4; u++)
            av[u] = *reinterpret_cast<const float4*>(&sA[(ty + 8 * u) * TPAD + k]);
#pragma unroll
        for (int u = 0; u < 4; u++)
            bv[u] = *reinterpret_cast<const float4*>(&sB[(tx + 8 * u) * TPAD + k]);

#pragma unroll
        for (int ii = 0; ii < 4; ii++) {
            const float2 a01 = *reinterpret_cast<const float2*>(&av[ii].x);
            const float2 a23 = *reinterpret_cast<const float2*>(&av[ii].z);
#pragma unroll
            for (int jj = 0; jj < 4; jj++) {
                const float2 b01 = *reinterpret_cast<const float2*>(&bv[jj].x);
                const float2 b23 = *reinterpret_cast<const float2*>(&bv[jj].z);
                float2 t01 = add2(a01, b01);
                float2 t23 = add2(a23, b23);
                t01.x = fmaxf(t01.x, 0.f); t01.y = fmaxf(t01.y, 0.f);
                t23.x = fmaxf(t23.x, 0.f); t23.y = fmaxf(t23.y, 0.f);
                acc[ii][jj] = fma2(t01, w01, acc[ii][jj]);
                acc[ii][jj] = fma2(t23, w23, acc[ii][jj]);
            }
        }
    }

#pragma unroll
    for (int ii = 0; ii < 4; ii++) {
        const int i = i0 + ty + 8 * ii;
#pragma unroll
        for (int jj = 0; jj < 4; jj++) {
            const int j = j0 + tx + 8 * jj;
            if (j == i) continue;
            const int e = i * (Nn - 1) + j - (j > i ? 1 : 0);
            const float x = acc[ii][jj].x + acc[ii][jj].y;   // b2 already folded
            const float w = 1.0f / (1.0f + __expf(-x));
            out[2 * EE + e] = w;
        }
    }
}

extern "C" void kernel_launch(void* const* d_in, const int* in_sizes, int n_in,
                              void* d_out, int out_size) {
    const float* emb = (const float*)d_in[0];  // [1024, 64]
    const float* W1  = (const float*)d_in[1];  // [128, 64]
    const float* b1  = (const float*)d_in[2];  // [64]
    const float* W2  = (const float*)d_in[3];  // [64, 1]
    const float* b2  = (const float*)d_in[4];  // [1]
    float* out = (float*)d_out;

    prep_kernel<<<128, 256>>>(emb, W1, b1, out);
    pair_kernel<<<dim3(32, 32), 64>>>(W2, b2, out);
}

// round 3
// speedup vs baseline: 1.0425x; 1.0110x over previous
#include <cuda_runtime.h>

// Problem constants: N=1024 agents, H=64 hidden.
#define Nn 1024
#define Hh 64
#define EE (Nn * (Nn - 1))   // 1047552 edges

// Factored first layer:
//   gA[i][k] = b1[k] + sum_c emb[i][c] * W1[c][k]
//   gB[j][k] =         sum_c emb[j][c] * W1[64+c][k]
__device__ float gA[Nn * Hh];
__device__ float gB[Nn * Hh];

// ---- packed f32x2 helpers (sm_10x; ptxas never auto-fuses these) -----------
__device__ __forceinline__ float2 add2(float2 a, float2 b) {
    float2 d;
    asm("add.rn.f32x2 %0, %1, %2;"
        : "=l"(*reinterpret_cast<unsigned long long*>(&d))
        : "l"(*reinterpret_cast<const unsigned long long*>(&a)),
          "l"(*reinterpret_cast<const unsigned long long*>(&b)));
    return d;
}
__device__ __forceinline__ float2 fma2(float2 a, float2 b, float2 c) {
    float2 d;
    asm("fma.rn.f32x2 %0, %1, %2, %3;"
        : "=l"(*reinterpret_cast<unsigned long long*>(&d))
        : "l"(*reinterpret_cast<const unsigned long long*>(&a)),
          "l"(*reinterpret_cast<const unsigned long long*>(&b)),
          "l"(*reinterpret_cast<const unsigned long long*>(&c)));
    return d;
}

// ---------------------------------------------------------------------------
// Kernel 1: gA/gB = emb @ [W1_top | W1_bot]  +  the two edge_index planes.
// 256 blocks x 256 threads = 2048 warps. Warps 0..1023 each own one emb row
// (lanes cover the 128 output cols in float4 quads). ALL 65536 threads share
// the index-plane stores (4 quads each).
// ---------------------------------------------------------------------------
__global__ void prep_kernel(const float* __restrict__ emb,
                            const float* __restrict__ W1,
                            const float* __restrict__ b1,
                            float* __restrict__ out) {
    const int t = threadIdx.x;
    const int gw = blockIdx.x * 8 + (t >> 5);    // global warp id: 0..2047
    const int lane = t & 31;

    if (gw < Nn) {
        const int row = gw;
        const int m = lane * 4;
        const int half = m >> 6;
        const int k = m & 63;
        const float* w1base = W1 + half * Hh * Hh;

        float acc0 = 0.f, acc1 = 0.f, acc2 = 0.f, acc3 = 0.f;
#pragma unroll
        for (int c = 0; c < Hh; c += 4) {
            const float4 e4 = *reinterpret_cast<const float4*>(emb + row * Hh + c);
            const float4 w0 = *reinterpret_cast<const float4*>(w1base + (c + 0) * Hh + k);
            const float4 w1v = *reinterpret_cast<const float4*>(w1base + (c + 1) * Hh + k);
            const float4 w2v = *reinterpret_cast<const float4*>(w1base + (c + 2) * Hh + k);
            const float4 w3v = *reinterpret_cast<const float4*>(w1base + (c + 3) * Hh + k);
            acc0 = fmaf(e4.x, w0.x, acc0); acc0 = fmaf(e4.y, w1v.x, acc0);
            acc0 = fmaf(e4.z, w2v.x, acc0); acc0 = fmaf(e4.w, w3v.x, acc0);
            acc1 = fmaf(e4.x, w0.y, acc1); acc1 = fmaf(e4.y, w1v.y, acc1);
            acc1 = fmaf(e4.z, w2v.y, acc1); acc1 = fmaf(e4.w, w3v.y, acc1);
            acc2 = fmaf(e4.x, w0.z, acc2); acc2 = fmaf(e4.y, w1v.z, acc2);
            acc2 = fmaf(e4.z, w2v.z, acc2); acc2 = fmaf(e4.w, w3v.z, acc2);
            acc3 = fmaf(e4.x, w0.w, acc3); acc3 = fmaf(e4.y, w1v.w, acc3);
            acc3 = fmaf(e4.z, w2v.w, acc3); acc3 = fmaf(e4.w, w3v.w, acc3);
        }

        float4 o;
        if (half == 0) {
            const float4 bb = *reinterpret_cast<const float4*>(b1 + k);
            o.x = acc0 + bb.x; o.y = acc1 + bb.y; o.z = acc2 + bb.z; o.w = acc3 + bb.w;
            *reinterpret_cast<float4*>(&gA[row * Hh + k]) = o;
        } else {
            o.x = acc0; o.y = acc1; o.z = acc2; o.w = acc3;
            *reinterpret_cast<float4*>(&gB[row * Hh + k]) = o;
        }
    }

    // --- edge_index planes: out[e] = i, out[E+e] = j ---
    // e = i*1023 + (j - (j>i));  inverse: i = e/1023, r = e%1023, j = r + (r>=i)
    const unsigned tid = blockIdx.x * 256 + t;       // 65536 threads
    const unsigned nquads = EE / 4;                  // 261888
    for (unsigned q = tid; q < nquads; q += 65536) {
        const unsigned e0 = q * 4;
        float4 vi, vj;
        float* pi = &vi.x;
        float* pj = &vj.x;
#pragma unroll
        for (int u = 0; u < 4; u++) {
            const unsigned e = e0 + u;
            const unsigned i = e / 1023u;
            const unsigned r = e - i * 1023u;
            const unsigned j = r + (r >= i ? 1u : 0u);
            pi[u] = (float)i;
            pj[u] = (float)j;
        }
        *reinterpret_cast<float4*>(out + e0) = vi;
        *reinterpret_cast<float4*>(out + EE + e0) = vj;
    }
}

// ---------------------------------------------------------------------------
// Kernel 2: per-pair MLP. Grid 32x32 = 1024 CTAs, 128 threads each
// (131K threads total -> ~28 warps/SM, 2x round-2 occupancy).
// Tile 32(i) x 32(j); micro-tile 4x2 per thread:
//   tx = t&15, ty = t>>4;  i = i0 + ty + 8*ii (ii<4),  j = j0 + tx + 16*jj (jj<2)
// SMEM stride 76 floats: A loads broadcast within 8-lane phases; B loads walk
// the full period-8 cycle of 48*r mod 128 -> conflict-free LDS.128.
// Inner math packed f32x2: per pair per 4k = 2 ADD2 + 4 FMNMX + 2 FMA2.
// ---------------------------------------------------------------------------
#define TS 32
#define TPAD 76

__global__ void __launch_bounds__(128) pair_kernel(const float* __restrict__ W2,
                                                   const float* __restrict__ b2ptr,
                                                   float* __restrict__ out) {
    __shared__ float sA[TS * TPAD];
    __shared__ float sB[TS * TPAD];
    __shared__ float sW2[64];

    const int t = threadIdx.x;
    const int tx = t & 15;
    const int ty = t >> 4;
    const int i0 = blockIdx.y * TS;
    const int j0 = blockIdx.x * TS;

    // Cooperative loads: 2 tiles x 512 float4 / 128 threads = 8 float4 each.
#pragma unroll
    for (int q = t; q < 2 * TS * 16; q += 128) {
        const int which = q >> 9;              // 0 -> A, 1 -> B
        const int r = (q >> 4) & 31;
        const int c4 = (q & 15) * 4;
        const float* src = which ? &gB[(j0 + r) * Hh + c4] : &gA[(i0 + r) * Hh + c4];
        float* dst = which ? &sB[r * TPAD + c4] : &sA[r * TPAD + c4];
        *reinterpret_cast<float4*>(dst) = *reinterpret_cast<const float4*>(src);
    }
    if (t < 64) sW2[t] = W2[t];
    __syncthreads();

    const float b2 = b2ptr[0];
    float2 acc[4][2];
#pragma unroll
    for (int ii = 0; ii < 4; ii++)
#pragma unroll
        for (int jj = 0; jj < 2; jj++)
            acc[ii][jj] = make_float2(b2, 0.f);   // fold b2 into the lo half

#pragma unroll 4
    for (int k = 0; k < Hh; k += 4) {
        const float4 wq = *reinterpret_cast<const float4*>(&sW2[k]);
        const float2 w01 = *reinterpret_cast<const float2*>(&wq.x);
        const float2 w23 = *reinterpret_cast<const float2*>(&wq.z);

        float4 av[4], bv[2];
#pragma unroll
        for (int u = 0; u < 4; u++)
            av[u] = *reinterpret_cast<const float4*>(&sA[(ty + 8 * u) * TPAD + k]);
#pragma unroll
        for (int u = 0; u < 2; u++)
            bv[u] = *reinterpret_cast<const float4*>(&sB[(tx + 16 * u) * TPAD + k]);

#pragma unroll
        for (int ii = 0; ii < 4; ii++) {
            const float2 a01 = *reinterpret_cast<const float2*>(&av[ii].x);
            const float2 a23 = *reinterpret_cast<const float2*>(&av[ii].z);
#pragma unroll
            for (int jj = 0; jj < 2; jj++) {
                const float2 b01 = *reinterpret_cast<const float2*>(&bv[jj].x);
                const float2 b23 = *reinterpret_cast<const float2*>(&bv[jj].z);
                float2 t01 = add2(a01, b01);
                float2 t23 = add2(a23, b23);
                t01.x = fmaxf(t01.x, 0.f); t01.y = fmaxf(t01.y, 0.f);
                t23.x = fmaxf(t23.x, 0.f); t23.y = fmaxf(t23.y, 0.f);
                acc[ii][jj] = fma2(t01, w01, acc[ii][jj]);
                acc[ii][jj] = fma2(t23, w23, acc[ii][jj]);
            }
        }
    }

#pragma unroll
    for (int ii = 0; ii < 4; ii++) {
        const int i = i0 + ty + 8 * ii;
#pragma unroll
        for (int jj = 0; jj < 2; jj++) {
            const int j = j0 + tx + 16 * jj;
            if (j == i) continue;
            const int e = i * (Nn - 1) + j - (j > i ? 1 : 0);
            const float x = acc[ii][jj].x + acc[ii][jj].y;   // b2 already folded
            const float w = 1.0f / (1.0f + __expf(-x));
            out[2 * EE + e] = w;
        }
    }
}

extern "C" void kernel_launch(void* const* d_in, const int* in_sizes, int n_in,
                              void* d_out, int out_size) {
    const float* emb = (const float*)d_in[0];  // [1024, 64]
    const float* W1  = (const float*)d_in[1];  // [128, 64]
    const float* b1  = (const float*)d_in[2];  // [64]
    const float* W2  = (const float*)d_in[3];  // [64, 1]
    const float* b2  = (const float*)d_in[4];  // [1]
    float* out = (float*)d_out;

    prep_kernel<<<256, 256>>>(emb, W1, b1, out);
    pair_kernel<<<dim3(32, 32), 128>>>(W2, b2, out);
}

// round 4
// speedup vs baseline: 1.1199x; 1.0743x over previous
#include <cuda_runtime.h>

// Problem constants: N=1024 agents, H=64 hidden.
#define Nn 1024
#define Hh 64
#define EE (Nn * (Nn - 1))   // 1047552 edges

// Factored first layer:
//   gA[i][k] = b1[k] + sum_c emb[i][c] * W1[c][k]
//   gB[j][k] =         sum_c emb[j][c] * W1[64+c][k]
__device__ float gA[Nn * Hh];
__device__ float gB[Nn * Hh];

// ---- packed f32x2 helpers (sm_10x; ptxas never auto-fuses these) -----------
__device__ __forceinline__ float2 add2(float2 a, float2 b) {
    float2 d;
    asm("add.rn.f32x2 %0, %1, %2;"
        : "=l"(*reinterpret_cast<unsigned long long*>(&d))
        : "l"(*reinterpret_cast<const unsigned long long*>(&a)),
          "l"(*reinterpret_cast<const unsigned long long*>(&b)));
    return d;
}
__device__ __forceinline__ float2 fma2(float2 a, float2 b, float2 c) {
    float2 d;
    asm("fma.rn.f32x2 %0, %1, %2, %3;"
        : "=l"(*reinterpret_cast<unsigned long long*>(&d))
        : "l"(*reinterpret_cast<const unsigned long long*>(&a)),
          "l"(*reinterpret_cast<const unsigned long long*>(&b)),
          "l"(*reinterpret_cast<const unsigned long long*>(&c)));
    return d;
}

// ---------------------------------------------------------------------------
// Kernel 1: gA/gB = emb @ [W1_top | W1_bot] with W1 staged in SMEM once per
// CTA (kills the 32 MB of per-warp W1 L2 re-reads). 128 CTAs x 256 threads;
// warp = one emb row, lanes cover the 128 output cols in float4 quads.
// ---------------------------------------------------------------------------
__global__ void __launch_bounds__(256) prep_kernel(const float* __restrict__ emb,
                                                   const float* __restrict__ W1,
                                                   const float* __restrict__ b1) {
    __shared__ float sW1[128 * 64];   // 32 KB

    const int t = threadIdx.x;
    // Stage W1: 2048 float4 / 256 threads = 8 each (coalesced).
#pragma unroll
    for (int q = t; q < 2048; q += 256)
        reinterpret_cast<float4*>(sW1)[q] = reinterpret_cast<const float4*>(W1)[q];
    __syncthreads();

    const int row = blockIdx.x * 8 + (t >> 5);
    const int lane = t & 31;
    const int m = lane * 4;
    const int half = m >> 6;
    const int k = m & 63;
    const float* w1base = sW1 + half * Hh * Hh;

    float acc0 = 0.f, acc1 = 0.f, acc2 = 0.f, acc3 = 0.f;
#pragma unroll
    for (int c = 0; c < Hh; c += 4) {
        const float4 e4 = *reinterpret_cast<const float4*>(emb + row * Hh + c);
        const float4 w0 = *reinterpret_cast<const float4*>(w1base + (c + 0) * Hh + k);
        const float4 w1v = *reinterpret_cast<const float4*>(w1base + (c + 1) * Hh + k);
        const float4 w2v = *reinterpret_cast<const float4*>(w1base + (c + 2) * Hh + k);
        const float4 w3v = *reinterpret_cast<const float4*>(w1base + (c + 3) * Hh + k);
        acc0 = fmaf(e4.x, w0.x, acc0); acc0 = fmaf(e4.y, w1v.x, acc0);
        acc0 = fmaf(e4.z, w2v.x, acc0); acc0 = fmaf(e4.w, w3v.x, acc0);
        acc1 = fmaf(e4.x, w0.y, acc1); acc1 = fmaf(e4.y, w1v.y, acc1);
        acc1 = fmaf(e4.z, w2v.y, acc1); acc1 = fmaf(e4.w, w3v.y, acc1);
        acc2 = fmaf(e4.x, w0.z, acc2); acc2 = fmaf(e4.y, w1v.z, acc2);
        acc2 = fmaf(e4.z, w2v.z, acc2); acc2 = fmaf(e4.w, w3v.z, acc2);
        acc3 = fmaf(e4.x, w0.w, acc3); acc3 = fmaf(e4.y, w1v.w, acc3);
        acc3 = fmaf(e4.z, w2v.w, acc3); acc3 = fmaf(e4.w, w3v.w, acc3);
    }

    float4 o;
    if (half == 0) {
        const float4 bb = *reinterpret_cast<const float4*>(b1 + k);
        o.x = acc0 + bb.x; o.y = acc1 + bb.y; o.z = acc2 + bb.z; o.w = acc3 + bb.w;
        *reinterpret_cast<float4*>(&gA[row * Hh + k]) = o;
    } else {
        o.x = acc0; o.y = acc1; o.z = acc2; o.w = acc3;
        *reinterpret_cast<float4*>(&gB[row * Hh + k]) = o;
    }
}

// ---------------------------------------------------------------------------
// Kernel 2: per-pair MLP with k-SPLIT for occupancy.
// Grid 64x32 = 2048 CTAs, 128 threads (262K threads, ~36-40 warps/SM).
// Tile: 32(i) x 16(j). Threads split into two 64-thread halves by k:
//   half 0 -> k in [0,32) (+b2 folded), half 1 -> k in [32,64).
// Within a half: tx = w&7, ty = w>>3;  i = i0+ty+8*ii (ii<4), j = j0+tx+8*jj
// (jj<2) -> 8 pairs/thread. Half 1 deposits partial sums in psum (lane-
// consecutive, conflict-free), then writes the i/j index planes; half 0 adds,
// applies sigmoid, writes the weight plane.
// SMEM stride 76: A rows hit bank quads {0,48,96,16}; B rows walk 48*r mod 128
// through all 32 banks exactly once -> conflict-free LDS.128.
// ---------------------------------------------------------------------------
#define TSI 32
#define TSJ 16
#define TPAD 76

__global__ void __launch_bounds__(128, 9) pair_kernel(const float* __restrict__ W2,
                                                      const float* __restrict__ b2ptr,
                                                      float* __restrict__ out) {
    __shared__ float sA[TSI * TPAD];
    __shared__ float sB[TSJ * TPAD];
    __shared__ float sW2[64];
    __shared__ float psum[8 * 64];

    const int t = threadIdx.x;
    const int half = t >> 6;
    const int w = t & 63;
    const int tx = w & 7;
    const int ty = w >> 3;
    const int i0 = blockIdx.y * TSI;
    const int j0 = blockIdx.x * TSJ;

    // Cooperative tile loads: sA 512 + sB 256 float4 = 768 / 128 threads = 6 each.
#pragma unroll
    for (int q = t; q < 768; q += 128) {
        if (q < 512) {
            const int r = q >> 4, c4 = (q & 15) * 4;
            *reinterpret_cast<float4*>(&sA[r * TPAD + c4]) =
                *reinterpret_cast<const float4*>(&gA[(i0 + r) * Hh + c4]);
        } else {
            const int q2 = q - 512;
            const int r = q2 >> 4, c4 = (q2 & 15) * 4;
            *reinterpret_cast<float4*>(&sB[r * TPAD + c4]) =
                *reinterpret_cast<const float4*>(&gB[(j0 + r) * Hh + c4]);
        }
    }
    if (t < 64) sW2[t] = W2[t];
    __syncthreads();

    const float b2 = b2ptr[0];
    const int kbase = half * 32;
    float2 acc[4][2];
#pragma unroll
    for (int ii = 0; ii < 4; ii++)
#pragma unroll
        for (int jj = 0; jj < 2; jj++)
            acc[ii][jj] = make_float2(half == 0 ? b2 : 0.f, 0.f);

#pragma unroll
    for (int c = 0; c < 32; c += 4) {
        const int k = kbase + c;
        const float4 wq = *reinterpret_cast<const float4*>(&sW2[k]);
        const float2 w01 = *reinterpret_cast<const float2*>(&wq.x);
        const float2 w23 = *reinterpret_cast<const float2*>(&wq.z);

        float4 av[4], bv[2];
#pragma unroll
        for (int u = 0; u < 4; u++)
            av[u] = *reinterpret_cast<const float4*>(&sA[(ty + 8 * u) * TPAD + k]);
#pragma unroll
        for (int u = 0; u < 2; u++)
            bv[u] = *reinterpret_cast<const float4*>(&sB[(tx + 8 * u) * TPAD + k]);

#pragma unroll
        for (int ii = 0; ii < 4; ii++) {
            const float2 a01 = *reinterpret_cast<const float2*>(&av[ii].x);
            const float2 a23 = *reinterpret_cast<const float2*>(&av[ii].z);
#pragma unroll
            for (int jj = 0; jj < 2; jj++) {
                const float2 b01 = *reinterpret_cast<const float2*>(&bv[jj].x);
                const float2 b23 = *reinterpret_cast<const float2*>(&bv[jj].z);
                float2 t01 = add2(a01, b01);
                float2 t23 = add2(a23, b23);
                t01.x = fmaxf(t01.x, 0.f); t01.y = fmaxf(t01.y, 0.f);
                t23.x = fmaxf(t23.x, 0.f); t23.y = fmaxf(t23.y, 0.f);
                acc[ii][jj] = fma2(t01, w01, acc[ii][jj]);
                acc[ii][jj] = fma2(t23, w23, acc[ii][jj]);
            }
        }
    }

    // Per-pair partial sums for this k-half.
    float s[8];
#pragma unroll
    for (int ii = 0; ii < 4; ii++)
#pragma unroll
        for (int jj = 0; jj < 2; jj++)
            s[ii * 2 + jj] = acc[ii][jj].x + acc[ii][jj].y;

    if (half == 1) {
#pragma unroll
        for (int p = 0; p < 8; p++)
            psum[p * 64 + w] = s[p];
    }
    __syncthreads();

    if (half == 1) {
        // Index planes (independent of the sums).
#pragma unroll
        for (int ii = 0; ii < 4; ii++) {
            const int i = i0 + ty + 8 * ii;
#pragma unroll
            for (int jj = 0; jj < 2; jj++) {
                const int j = j0 + tx + 8 * jj;
                if (j == i) continue;
                const int e = i * (Nn - 1) + j - (j > i ? 1 : 0);
                out[e] = (float)i;
                out[EE + e] = (float)j;
            }
        }
    } else {
        // Combine halves, sigmoid, weight plane.
#pragma unroll
        for (int ii = 0; ii < 4; ii++) {
            const int i = i0 + ty + 8 * ii;
#pragma unroll
            for (int jj = 0; jj < 2; jj++) {
                const int j = j0 + tx + 8 * jj;
                if (j == i) continue;
                const int p = ii * 2 + jj;
                const int e = i * (Nn - 1) + j - (j > i ? 1 : 0);
                const float x = s[p] + psum[p * 64 + w];
                out[2 * EE + e] = 1.0f / (1.0f + __expf(-x));
            }
        }
    }
}

extern "C" void kernel_launch(void* const* d_in, const int* in_sizes, int n_in,
                              void* d_out, int out_size) {
    const float* emb = (const float*)d_in[0];  // [1024, 64]
    const float* W1  = (const float*)d_in[1];  // [128, 64]
    const float* b1  = (const float*)d_in[2];  // [64]
    const float* W2  = (const float*)d_in[3];  // [64, 1]
    const float* b2  = (const float*)d_in[4];  // [1]
    float* out = (float*)d_out;

    prep_kernel<<<128, 256>>>(emb, W1, b1);
    pair_kernel<<<dim3(64, 32), 128>>>(W2, b2, out);
}

// round 6
// speedup vs baseline: 1.1755x; 1.0496x over previous
#include <cuda_runtime.h>

// Problem constants: N=1024 agents, H=64 hidden.
#define Nn 1024
#define Hh 64
#define EE (Nn * (Nn - 1))   // 1047552 edges

// Factored first layer:
//   gA[i][k] = b1[k] + sum_c emb[i][c] * W1[c][k]
//   gB[j][k] =         sum_c emb[j][c] * W1[64+c][k]
__device__ float gA[Nn * Hh];
__device__ float gB[Nn * Hh];

// ---- packed f32x2 helpers (sm_10x; only add/mul/fma exist packed) ----------
__device__ __forceinline__ float2 add2(float2 a, float2 b) {
    float2 d;
    asm("add.rn.f32x2 %0, %1, %2;"
        : "=l"(*reinterpret_cast<unsigned long long*>(&d))
        : "l"(*reinterpret_cast<const unsigned long long*>(&a)),
          "l"(*reinterpret_cast<const unsigned long long*>(&b)));
    return d;
}
__device__ __forceinline__ float2 fma2(float2 a, float2 b, float2 c) {
    float2 d;
    asm("fma.rn.f32x2 %0, %1, %2, %3;"
        : "=l"(*reinterpret_cast<unsigned long long*>(&d))
        : "l"(*reinterpret_cast<const unsigned long long*>(&a)),
          "l"(*reinterpret_cast<const unsigned long long*>(&b)),
          "l"(*reinterpret_cast<const unsigned long long*>(&c)));
    return d;
}

// ---------------------------------------------------------------------------
// Kernel 1: gA/gB = emb @ [W1_top | W1_bot] with W1 staged in SMEM once per
// CTA. 128 CTAs x 256 threads; warp = one emb row, lanes cover the 128
// output cols in float4 quads. Nothing else — index planes are written by
// the pair kernel's epilogue.
// ---------------------------------------------------------------------------
__global__ void __launch_bounds__(256) prep_kernel(const float* __restrict__ emb,
                                                   const float* __restrict__ W1,
                                                   const float* __restrict__ b1) {
    __shared__ float sW1[128 * 64];   // 32 KB

    const int t = threadIdx.x;
#pragma unroll
    for (int q = t; q < 2048; q += 256)
        reinterpret_cast<float4*>(sW1)[q] = reinterpret_cast<const float4*>(W1)[q];
    __syncthreads();

    const int row = blockIdx.x * 8 + (t >> 5);
    const int lane = t & 31;
    const int m = lane * 4;
    const int half = m >> 6;
    const int k = m & 63;
    const float* w1base = sW1 + half * Hh * Hh;

    float acc0 = 0.f, acc1 = 0.f, acc2 = 0.f, acc3 = 0.f;
#pragma unroll
    for (int c = 0; c < Hh; c += 4) {
        const float4 e4 = *reinterpret_cast<const float4*>(emb + row * Hh + c);
        const float4 w0 = *reinterpret_cast<const float4*>(w1base + (c + 0) * Hh + k);
        const float4 w1v = *reinterpret_cast<const float4*>(w1base + (c + 1) * Hh + k);
        const float4 w2v = *reinterpret_cast<const float4*>(w1base + (c + 2) * Hh + k);
        const float4 w3v = *reinterpret_cast<const float4*>(w1base + (c + 3) * Hh + k);
        acc0 = fmaf(e4.x, w0.x, acc0); acc0 = fmaf(e4.y, w1v.x, acc0);
        acc0 = fmaf(e4.z, w2v.x, acc0); acc0 = fmaf(e4.w, w3v.x, acc0);
        acc1 = fmaf(e4.x, w0.y, acc1); acc1 = fmaf(e4.y, w1v.y, acc1);
        acc1 = fmaf(e4.z, w2v.y, acc1); acc1 = fmaf(e4.w, w3v.y, acc1);
        acc2 = fmaf(e4.x, w0.z, acc2); acc2 = fmaf(e4.y, w1v.z, acc2);
        acc2 = fmaf(e4.z, w2v.z, acc2); acc2 = fmaf(e4.w, w3v.z, acc2);
        acc3 = fmaf(e4.x, w0.w, acc3); acc3 = fmaf(e4.y, w1v.w, acc3);
        acc3 = fmaf(e4.z, w2v.w, acc3); acc3 = fmaf(e4.w, w3v.w, acc3);
    }

    float4 o;
    if (half == 0) {
        const float4 bb = *reinterpret_cast<const float4*>(b1 + k);
        o.x = acc0 + bb.x; o.y = acc1 + bb.y; o.z = acc2 + bb.z; o.w = acc3 + bb.w;
        *reinterpret_cast<float4*>(&gA[row * Hh + k]) = o;
    } else {
        o.x = acc0; o.y = acc1; o.z = acc2; o.w = acc3;
        *reinterpret_cast<float4*>(&gB[row * Hh + k]) = o;
    }
}

// ---------------------------------------------------------------------------
// Kernel 2: per-pair MLP. Grid 32(j) x 64(i) = 2048 CTAs, 128 threads.
// Tile 16(i) x 32(j); 2x2 micro-tile per thread:
//   tx = t&15, ty = t>>4;  i = i0 + ty + 8*ii (ii<2),  j = j0 + tx + 16*jj (jj<2)
// Per k-chunk per thread: 2 A + 2 B + 1 W LDS.128, then 4 pairs x
// (2 ADD2 + 4 FMNMX + 2 FMA2).
// Bank check (stride 76 floats = 304B, per 8-lane phase): B rows walk
// 48*r mod 128 through all 8 quad-groups exactly once; A rows broadcast
// within a phase -> conflict-free LDS.128.
// Epilogue writes all three output planes (i, j, sigmoid weight).
// __launch_bounds__(128,10): regs<=51 -> ~40 resident warps/SM.
// ---------------------------------------------------------------------------
#define TSI 16
#define TSJ 32
#define TPAD 76

__global__ void __launch_bounds__(128, 10) pair_kernel(const float* __restrict__ W2,
                                                       const float* __restrict__ b2ptr,
                                                       float* __restrict__ out) {
    __shared__ float sA[TSI * TPAD];
    __shared__ float sB[TSJ * TPAD];
    __shared__ float sW2[64];

    const int t = threadIdx.x;
    const int tx = t & 15;
    const int ty = t >> 4;
    const int i0 = blockIdx.y * TSI;
    const int j0 = blockIdx.x * TSJ;

    // Cooperative tile loads: sA 256 + sB 512 float4 = 768 / 128 threads = 6 each.
#pragma unroll
    for (int q = t; q < 768; q += 128) {
        if (q < 256) {
            const int r = q >> 4, c4 = (q & 15) * 4;
            *reinterpret_cast<float4*>(&sA[r * TPAD + c4]) =
                *reinterpret_cast<const float4*>(&gA[(i0 + r) * Hh + c4]);
        } else {
            const int q2 = q - 256;
            const int r = q2 >> 4, c4 = (q2 & 15) * 4;
            *reinterpret_cast<float4*>(&sB[r * TPAD + c4]) =
                *reinterpret_cast<const float4*>(&gB[(j0 + r) * Hh + c4]);
        }
    }
    if (t < 64) sW2[t] = W2[t];
    __syncthreads();

    const float b2 = b2ptr[0];
    float2 acc[2][2];
#pragma unroll
    for (int ii = 0; ii < 2; ii++)
#pragma unroll
        for (int jj = 0; jj < 2; jj++)
            acc[ii][jj] = make_float2(b2, 0.f);   // fold b2 into lo half

#pragma unroll 4
    for (int k = 0; k < Hh; k += 4) {
        const float4 wq = *reinterpret_cast<const float4*>(&sW2[k]);
        const float2 w01 = *reinterpret_cast<const float2*>(&wq.x);
        const float2 w23 = *reinterpret_cast<const float2*>(&wq.z);

        float4 av[2], bv[2];
#pragma unroll
        for (int u = 0; u < 2; u++)
            av[u] = *reinterpret_cast<const float4*>(&sA[(ty + 8 * u) * TPAD + k]);
#pragma unroll
        for (int u = 0; u < 2; u++)
            bv[u] = *reinterpret_cast<const float4*>(&sB[(tx + 16 * u) * TPAD + k]);

#pragma unroll
        for (int ii = 0; ii < 2; ii++) {
            const float2 a01 = *reinterpret_cast<const float2*>(&av[ii].x);
            const float2 a23 = *reinterpret_cast<const float2*>(&av[ii].z);
#pragma unroll
            for (int jj = 0; jj < 2; jj++) {
                const float2 b01 = *reinterpret_cast<const float2*>(&bv[jj].x);
                const float2 b23 = *reinterpret_cast<const float2*>(&bv[jj].z);
                float2 t01 = add2(a01, b01);
                float2 t23 = add2(a23, b23);
                t01.x = fmaxf(t01.x, 0.f); t01.y = fmaxf(t01.y, 0.f);
                t23.x = fmaxf(t23.x, 0.f); t23.y = fmaxf(t23.y, 0.f);
                acc[ii][jj] = fma2(t01, w01, acc[ii][jj]);
                acc[ii][jj] = fma2(t23, w23, acc[ii][jj]);
            }
        }
    }

#pragma unroll
    for (int ii = 0; ii < 2; ii++) {
        const int i = i0 + ty + 8 * ii;
#pragma unroll
        for (int jj = 0; jj < 2; jj++) {
            const int j = j0 + tx + 16 * jj;
            if (j == i) continue;
            const int e = i * (Nn - 1) + j - (j > i ? 1 : 0);
            const float x = acc[ii][jj].x + acc[ii][jj].y;   // b2 already folded
            out[e] = (float)i;
            out[EE + e] = (float)j;
            out[2 * EE + e] = 1.0f / (1.0f + __expf(-x));
        }
    }
}

extern "C" void kernel_launch(void* const* d_in, const int* in_sizes, int n_in,
                              void* d_out, int out_size) {
    const float* emb = (const float*)d_in[0];  // [1024, 64]
    const float* W1  = (const float*)d_in[1];  // [128, 64]
    const float* b1  = (const float*)d_in[2];  // [64]
    const float* W2  = (const float*)d_in[3];  // [64, 1]
    const float* b2  = (const float*)d_in[4];  // [1]
    float* out = (float*)d_out;

    prep_kernel<<<128, 256>>>(emb, W1, b1);
    pair_kernel<<<dim3(32, 64), 128>>>(W2, b2, out);
}